// round 15
// baseline (speedup 1.0000x reference)
#include <cuda_runtime.h>

#define Dd      64
#define HALF    512
#define NT      256
#define SLOTS   4
#define SITE_F  8192          // floats per site
#define SITE_B  32768u

// dynamic SMEM layout (floats)
#define OFF_XS    (SLOTS * SITE_F)       // x slice: 2048
#define OFF_PARTS (OFF_XS + 2048)        // parts: 2 x 272
#define OFF_MBAR  (OFF_PARTS + 544)      // 4 mbarriers (u64) = 8 floats
#define SMEM_BYTES ((OFF_MBAR + 16) * 4)

typedef unsigned long long u64;

__device__ float g_vL[64 * Dd];
__device__ float g_wR[64 * Dd];
__device__ float g_Wt[HALF * 64 * 128];   // transposed W_right, 16MB scratch

__device__ __forceinline__ unsigned su(const void* p) {
    return (unsigned)__cvta_generic_to_shared(p);
}
__device__ __forceinline__ u64 pk2(float a, float b) {
    u64 r; asm("mov.b64 %0, {%1,%2};" : "=l"(r) : "f"(a), "f"(b)); return r;
}
__device__ __forceinline__ u64 fma2(u64 a, u64 b, u64 c) {
    u64 d; asm("fma.rn.f32x2 %0, %1, %2, %3;" : "=l"(d) : "l"(a), "l"(b), "l"(c)); return d;
}
__device__ __forceinline__ float2 up2(u64 v) {
    float2 f; asm("mov.b64 {%0,%1}, %2;" : "=f"(f.x), "=f"(f.y) : "l"(v)); return f;
}

// One 32KB bulk copy per site (single op -> no per-op overhead storm like R6).
__device__ __forceinline__ void issue_site(float* dstSlot, const float* src, u64* mb) {
    unsigned mba = su(mb);
    asm volatile("mbarrier.arrive.expect_tx.shared.b64 _, [%0], %1;"
                 :: "r"(mba), "r"(SITE_B) : "memory");
    asm volatile(
        "cp.async.bulk.shared::cluster.global.mbarrier::complete_tx::bytes "
        "[%0], [%1], %2, [%3];"
        :: "r"(su(dstSlot)), "l"(src), "r"(SITE_B), "r"(mba) : "memory");
}

__device__ __forceinline__ void wait_parity(u64* mb, int ph) {
    unsigned mba = su(mb);
    unsigned done;
    asm volatile(
        "{\n\t.reg .pred p;\n\t"
        "mbarrier.try_wait.parity.acquire.cta.shared::cta.b64 p, [%1], %2;\n\t"
        "selp.b32 %0, 1, 0, p;\n\t}"
        : "=r"(done) : "r"(mba), "r"(ph) : "memory");
    if (!done) {
        asm volatile(
            "{\n\t.reg .pred P1;\n\t"
            "WL_%=:\n\t"
            "mbarrier.try_wait.parity.acquire.cta.shared::cta.b64 P1, [%0], %1, 0x989680;\n\t"
            "@P1 bra.uni WD_%=;\n\t"
            "bra.uni WL_%=;\n\t"
            "WD_%=:\n\t}"
            :: "r"(mba), "r"(ph) : "memory");
    }
}

// g_Wt[s][r][2l+i] = Wr[s][l][2r+i]
__global__ void __launch_bounds__(256, 4)
transpose_kernel(const float* __restrict__ Wr)
{
    __shared__ float tile[64 * 132];
    const int s = blockIdx.x;
    const float* in = Wr + (size_t)s * 8192;
    float* out = g_Wt + (size_t)s * 8192;
    for (int idx = threadIdx.x; idx < 8192; idx += 256)
        tile[(idx >> 7) * 132 + (idx & 127)] = in[idx];
    __syncthreads();
    for (int idx = threadIdx.x; idx < 8192; idx += 256) {
        int r = idx >> 7, c = idx & 127;
        out[idx] = tile[(c >> 1) * 132 + 2 * r + (c & 1)];
    }
}

// R13 compute structure; W staged by TMA bulk into a 4-slot SMEM ring.
// warp w = qh*2+rh; lane = rr*8+qs. Thread: rows crow0..crow0+7, q pair q0,q0+1.
__global__ void __launch_bounds__(NT, 1)
chain_kernel(const float* __restrict__ x, const float* __restrict__ Wl)
{
    extern __shared__ float sm[];
    float* smW   = sm;                    // [SLOTS][8192] raw site images
    float* xs    = sm + OFF_XS;           // [2][1024]
    float* parts = sm + OFF_PARTS;        // [2][272]
    u64*   mbar  = (u64*)(sm + OFF_MBAR); // [SLOTS]

    const int t     = threadIdx.x;
    const int side  = blockIdx.x >> 5;    // 32 CTAs per side
    const int gb    = (blockIdx.x & 31) * 2;
    const int w     = t >> 5, lane = t & 31;
    const int qh    = w >> 1, rh = w & 1;
    const int rr    = lane >> 3, qs = lane & 7;
    const int q0    = qh * 16 + qs * 2;
    const int crow0 = rh * 32 + rr * 8;
    const int Woff  = crow0 * 128 + 2 * q0;   // float offset of thread's first row chunk

    for (int i = t; i < 2048; i += NT) {
        int b2 = i >> 10;
        xs[i] = x[(gb + b2) * 2048 + side * 1024 + (i & 1023)];
    }
    for (int i = t; i < 2 * 272; i += NT) parts[i] = 0.f;
    if (t < SLOTS)
        asm volatile("mbarrier.init.shared.b64 [%0], %1;"
                     :: "r"(su(mbar + t)), "r"(1) : "memory");
    __syncthreads();
    if (t < 2) parts[t * 68] = 1.f;       // buf0: v = e0 per batch
    __syncthreads();

    const float* Wbase = side ? (g_Wt + (size_t)(HALF - 1) * 8192) : Wl;
    const long   strd  = side ? -8192 : 8192;

    // prologue: sites 0,1 into slots 0,1
    if (t == 0) {
        issue_site(smW,          Wbase,               mbar + 0);
        issue_site(smW + SITE_F, Wbase + strd,        mbar + 1);
    }

    for (int i = 0; i < HALF; ++i) {
        const int slot = i & 3;
        wait_parity(mbar + slot, (i >> 2) & 1);
        const float* Wc = smW + slot * SITE_F + Woff;

        const int sl = side ? (HALF - 1 - i) : i;
        const float* pin  = parts + (i & 1) * 272;
        float*       pout = parts + ((i + 1) & 1) * 272;

        float4 a0 = *(const float4*)(pin + crow0);
        float4 a1 = *(const float4*)(pin + crow0 + 4);
        float4 b0 = *(const float4*)(pin + 136 + crow0);
        float4 b1 = *(const float4*)(pin + 136 + crow0 + 4);
        float4 c0 = *(const float4*)(pin + 68 + crow0);
        float4 c1 = *(const float4*)(pin + 68 + crow0 + 4);
        float4 d0 = *(const float4*)(pin + 204 + crow0);
        float4 d1 = *(const float4*)(pin + 204 + crow0 + 4);
        float vs0[8], vs1[8];
        vs0[0]=a0.x+b0.x; vs0[1]=a0.y+b0.y; vs0[2]=a0.z+b0.z; vs0[3]=a0.w+b0.w;
        vs0[4]=a1.x+b1.x; vs0[5]=a1.y+b1.y; vs0[6]=a1.z+b1.z; vs0[7]=a1.w+b1.w;
        vs1[0]=c0.x+d0.x; vs1[1]=c0.y+d0.y; vs1[2]=c0.z+d0.z; vs1[3]=c0.w+d0.w;
        vs1[4]=c1.x+d1.x; vs1[5]=c1.y+d1.y; vs1[6]=c1.z+d1.z; vs1[7]=c1.w+d1.w;

        u64 acc00 = 0ull, acc01 = 0ull, acc10 = 0ull, acc11 = 0ull;
#pragma unroll
        for (int g = 0; g < 8; g++) {
            ulonglong2 ww = *(const ulonglong2*)(Wc + g * 128);
            u64 v0 = pk2(vs0[g], vs0[g]);
            u64 v1 = pk2(vs1[g], vs1[g]);
            acc00 = fma2(v0, ww.x, acc00); acc01 = fma2(v0, ww.y, acc01);
            acc10 = fma2(v1, ww.x, acc10); acc11 = fma2(v1, ww.y, acc11);
        }
        float2 xv0 = *(const float2*)(xs + sl * 2);
        float2 xv1 = *(const float2*)(xs + 1024 + sl * 2);
        float2 A;
        A = up2(acc00); float p00 = xv0.x * A.x + xv0.y * A.y;
        A = up2(acc01); float p01 = xv0.x * A.x + xv0.y * A.y;
        A = up2(acc10); float p10 = xv1.x * A.x + xv1.y * A.y;
        A = up2(acc11); float p11 = xv1.x * A.x + xv1.y * A.y;
        p00 += __shfl_xor_sync(~0u, p00, 8);  p00 += __shfl_xor_sync(~0u, p00, 16);
        p01 += __shfl_xor_sync(~0u, p01, 8);  p01 += __shfl_xor_sync(~0u, p01, 16);
        p10 += __shfl_xor_sync(~0u, p10, 8);  p10 += __shfl_xor_sync(~0u, p10, 16);
        p11 += __shfl_xor_sync(~0u, p11, 8);  p11 += __shfl_xor_sync(~0u, p11, 16);
        if (rr == 0) {
            *(float2*)(pout + rh * 136 + q0)      = make_float2(p00, p01);
            *(float2*)(pout + rh * 136 + 68 + q0) = make_float2(p10, p11);
        }
        __syncthreads();   // v published AND slot (i+2)&3 fully consumed (step i-2)

        if (t == 0 && i + 2 < HALF) {
            int nslot = (i + 2) & 3;
            issue_site(smW + nslot * SITE_F, Wbase + (long)(i + 2) * strd, mbar + nslot);
        }
    }

    // final v in buffer 0: sum the two rh partials
    if (t < 128) {
        int b = t >> 6, q = t & 63;
        float vfin = parts[b * 68 + q] + parts[136 + b * 68 + q];
        (side ? g_wR : g_vL)[(gb + b) * Dd + q] = vfin;
    }
}

// out[b,o] = sum_{l,r} vL[b,l] * core[o,l,r] * wR[b,r]
__global__ void __launch_bounds__(320, 4)
combine_kernel(const float* __restrict__ core, float* __restrict__ out)
{
    __shared__ float vsh[Dd], wsh[Dd];
    const int b    = blockIdx.x;
    const int t    = threadIdx.x;
    const int o    = t >> 5;
    const int lane = t & 31;

    if (t < Dd) { vsh[t] = g_vL[b * Dd + t]; wsh[t] = g_wR[b * Dd + t]; }
    __syncthreads();

    const float* co = core + o * (Dd * Dd);
    float a0 = 0.f, a1 = 0.f;
#pragma unroll 8
    for (int l = 0; l < Dd; ++l) {
        float vl = vsh[l];
        a0 = fmaf(vl, co[l * Dd + lane],      a0);
        a1 = fmaf(vl, co[l * Dd + lane + 32], a1);
    }
    float p = a0 * wsh[lane] + a1 * wsh[lane + 32];
#pragma unroll
    for (int off = 16; off; off >>= 1)
        p += __shfl_down_sync(0xffffffffu, p, off);
    if (lane == 0) out[b * 10 + o] = p;
}

extern "C" void kernel_launch(void* const* d_in, const int* in_sizes, int n_in,
                              void* d_out, int out_size)
{
    const float* x    = (const float*)d_in[0];
    const float* Wl   = (const float*)d_in[1];
    const float* core = (const float*)d_in[2];
    const float* Wr   = (const float*)d_in[3];
    float* out = (float*)d_out;

    cudaFuncSetAttribute(chain_kernel,
                         cudaFuncAttributeMaxDynamicSharedMemorySize, SMEM_BYTES);

    transpose_kernel<<<HALF, 256>>>(Wr);
    chain_kernel<<<64, NT, SMEM_BYTES>>>(x, Wl);
    combine_kernel<<<64, 320>>>(core, out);
}